// round 6
// baseline (speedup 1.0000x reference)
#include <cuda_runtime.h>

#define Bb     8
#define Nn     3136
#define Cc     64
#define CI     32
#define BNROWS 25088          // Bb * Nn
#define LAMF   0.1f
#define HSTEP  0.05f
#define BNEPS  1e-3f
#define INVN   (1.0f / 3136.0f)

// ---- scratch (static device globals; no allocation) ----
__device__ float d_theta[BNROWS * CI];
__device__ float d_phi[BNROWS * CI];
__device__ float d_phisum[Bb * CI];
__device__ float d_pspart[784 * CI];     // per-block phi-sum partials
__device__ float d_M[2][Bb * 2048];      // phi^T g per iter; zeroed in k_theta_phi
__device__ float d_g1[BNROWS * Cc];

// ===========================================================================
// K1: theta/phi = x @ Wt/Wp + bias; per-block phi-sum partials; blocks 0-31
// zero both d_M buffers (this kernel never touches d_M otherwise).
__global__ void __launch_bounds__(256) k_theta_phi(
        const float* __restrict__ x,
        const float* __restrict__ Wt, const float* __restrict__ bt,
        const float* __restrict__ Wp, const float* __restrict__ bp) {
    __shared__ float sx[32 * 64];
    __shared__ float sWt[32 * 68];
    __shared__ float sWp[32 * 68];
    __shared__ float sp[32];
    int t  = threadIdx.x;
    int gb = blockIdx.x;
    int r0 = gb * 32;

    if (gb < 32) {   // zero both M buffers: 8192 float4 total
        float4 z = make_float4(0.f, 0.f, 0.f, 0.f);
        ((float4*)d_M)[gb * 256 + t] = z;
    }
    {
        const float4* src = (const float4*)(x + r0 * 64);
        ((float4*)sx)[t]       = src[t];
        ((float4*)sx)[t + 256] = src[t + 256];
    }
    for (int e = t; e < 2048; e += 256) {   // weights transposed
        int k = e >> 5, d = e & 31;
        sWt[d * 68 + k] = Wt[e];
        sWp[d * 68 + k] = Wp[e];
    }
    if (t < 32) sp[t] = 0.f;
    __syncthreads();

    int w = t >> 5, d = t & 31;
    float th[4], ph[4];
    float bt_d = bt[d], bp_d = bp[d];
#pragma unroll
    for (int j = 0; j < 4; j++) { th[j] = bt_d; ph[j] = bp_d; }

    const float* xr = sx + w * 4 * 64;
    const float* wt = sWt + d * 68;
    const float* wp = sWp + d * 68;
#pragma unroll
    for (int k = 0; k < 64; k += 4) {
        float4 a = *(const float4*)(wt + k);
        float4 b = *(const float4*)(wp + k);
#pragma unroll
        for (int j = 0; j < 4; j++) {
            float4 xv = *(const float4*)(xr + j * 64 + k);
            th[j] = fmaf(xv.x, a.x, th[j]); th[j] = fmaf(xv.y, a.y, th[j]);
            th[j] = fmaf(xv.z, a.z, th[j]); th[j] = fmaf(xv.w, a.w, th[j]);
            ph[j] = fmaf(xv.x, b.x, ph[j]); ph[j] = fmaf(xv.y, b.y, ph[j]);
            ph[j] = fmaf(xv.z, b.z, ph[j]); ph[j] = fmaf(xv.w, b.w, ph[j]);
        }
    }
    int r = r0 + w * 4;
    float phs = 0.f;
#pragma unroll
    for (int j = 0; j < 4; j++) {
        d_theta[(r + j) * 32 + d] = th[j];
        d_phi[(r + j) * 32 + d]   = ph[j];
        phs += ph[j];
    }
    atomicAdd(&sp[d], phs);
    __syncthreads();
    if (t < 32) d_pspart[gb * 32 + t] = sp[t];
}

// ===========================================================================
// K2: M0[b] += phi[b]^T @ x[b]. 32 rows/block, grid 784 for occupancy.
// chunk-0 blocks finalize d_phisum (idempotent; reads prior-kernel data).
__global__ void __launch_bounds__(256) k_reduceM0(const float* __restrict__ x) {
    __shared__ float sph[32 * 32];
    __shared__ float sg[32 * 64];
    int t     = threadIdx.x;
    int b     = blockIdx.x / 98;
    int chunk = blockIdx.x % 98;
    int row0  = b * Nn + chunk * 32;

    if (chunk == 0 && t < 32) {
        float a = 0.f;
        for (int j = 0; j < 98; j++) a += d_pspart[(b * 98 + j) * 32 + t];
        d_phisum[b * 32 + t] = a;
    }

    ((float4*)sph)[t] = ((const float4*)(d_phi + row0 * 32))[t];
    {
        const float4* src = (const float4*)(x + row0 * 64);
        ((float4*)sg)[t]       = src[t];
        ((float4*)sg)[t + 256] = src[t + 256];
    }
    __syncthreads();

    int d = t & 31, cb = (t >> 5) * 8;
    float acc[8] = {0.f, 0.f, 0.f, 0.f, 0.f, 0.f, 0.f, 0.f};
#pragma unroll 8
    for (int r = 0; r < 32; r++) {
        float pd = sph[r * 32 + d];
        float4 g0 = *(const float4*)(sg + r * 64 + cb);
        float4 g1v = *(const float4*)(sg + r * 64 + cb + 4);
        acc[0] = fmaf(pd, g0.x, acc[0]);  acc[1] = fmaf(pd, g0.y, acc[1]);
        acc[2] = fmaf(pd, g0.z, acc[2]);  acc[3] = fmaf(pd, g0.w, acc[3]);
        acc[4] = fmaf(pd, g1v.x, acc[4]); acc[5] = fmaf(pd, g1v.y, acc[5]);
        acc[6] = fmaf(pd, g1v.z, acc[6]); acc[7] = fmaf(pd, g1v.w, acc[7]);
    }
    float* Mb = d_M[0] + b * 2048 + d * 64 + cb;
#pragma unroll
    for (int q = 0; q < 8; q++) atomicAdd(&Mb[q], acc[q]);
}

// ===========================================================================
// K3/K4: two-phase apply.
//   phase1: raw = theta @ M (K=32); fg = (lam/N)*raw - (s/N)*g
//   phase2: o = fg @ W + bias; BN; ReLU; out = x + 0.05*o
// If DO_M1: also accumulate partial M1 = phi^T out (atomics) from smem-stashed
// out tile; apply(iter1) reads d_M[1] next launch (stream-ordered, no fences).
template<int ITER, int DO_M1>
__global__ void __launch_bounds__(256) k_apply(
        const float* __restrict__ x,
        const float* __restrict__ Wst, const float* __restrict__ bst,
        const float* __restrict__ gam, const float* __restrict__ bet,
        const float* __restrict__ mmean, const float* __restrict__ mvar,
        float* __restrict__ out_ext) {
    const float* gin = ITER ? d_g1 : x;
    float* out       = ITER ? out_ext : d_g1;

    __shared__ float sm[8800];
    float* sAt  = sm;          // theta^T [k=32][row 64] pad 68   (2176)
    float* sM   = sm + 2176;   // M [k=32][col 64] pad 68          (2176)
    float* sW   = sm + 4352;   // W [k=64][col 64] pad 68          (4352)
    float* sfgT = sm;          // fg^T [k=64][row 64] pad 68, overlays sAt+sM
    float* SOUT = sm;          // out tile [row 64][c 64] pad 68   (4352), after phase2
    float* SPHI = sm + 4352;   // phi chunk [row 64][d 32]         (2048), overlays sW
    float* ss   = sm + 8704;   // 64
    float* sps  = sm + 8768;   // 32

    int t  = threadIdx.x;
    int r0 = blockIdx.x * 64;
    int b  = blockIdx.x / 49;

    // stage theta^T
#pragma unroll
    for (int j = 0; j < 2; j++) {
        int e = t + j * 256;
        int r = e >> 3, dd = (e & 7) * 4;
        float4 v = ((const float4*)(d_theta + r0 * 32))[e];
        sAt[(dd + 0) * 68 + r] = v.x;
        sAt[(dd + 1) * 68 + r] = v.y;
        sAt[(dd + 2) * 68 + r] = v.z;
        sAt[(dd + 3) * 68 + r] = v.w;
    }
    // stage M
    const float* Mi = d_M[ITER] + b * 2048;
#pragma unroll
    for (int j = 0; j < 2; j++) {
        int e = t + j * 256;
        int k = e >> 4, c4 = (e & 15) * 4;
        *(float4*)(sM + k * 68 + c4) = ((const float4*)Mi)[e];
    }
    // stage W
    const float* Wi = Wst + ITER * 4096;
#pragma unroll
    for (int j = 0; j < 4; j++) {
        int e = t + j * 256;
        int k = e >> 4, c4 = (e & 15) * 4;
        *(float4*)(sW + k * 68 + c4) = ((const float4*)Wi)[e];
    }
    if (t < 32) sps[t] = d_phisum[b * 32 + t];
    __syncthreads();

    if (t < 64) {   // -(s/N) per row, s = LAM * theta . phisum
        float a = 0.f;
#pragma unroll
        for (int k = 0; k < 32; k++) a = fmaf(sAt[k * 68 + t], sps[k], a);
        ss[t] = a * (-LAMF * INVN);
    }
    __syncthreads();

    int tx = t & 15, ty = t >> 4;
    int rr = ty * 4, cc = tx * 4;

    // ---- phase 1: raw = theta @ M (K=32) ----
    float fg[4][4];
#pragma unroll
    for (int i = 0; i < 4; i++)
#pragma unroll
        for (int j = 0; j < 4; j++) fg[i][j] = 0.f;

#pragma unroll 8
    for (int k = 0; k < 32; k++) {
        float4 a  = *(const float4*)(sAt + k * 68 + rr);
        float4 bv = *(const float4*)(sM + k * 68 + cc);
        fg[0][0] = fmaf(a.x, bv.x, fg[0][0]); fg[0][1] = fmaf(a.x, bv.y, fg[0][1]);
        fg[0][2] = fmaf(a.x, bv.z, fg[0][2]); fg[0][3] = fmaf(a.x, bv.w, fg[0][3]);
        fg[1][0] = fmaf(a.y, bv.x, fg[1][0]); fg[1][1] = fmaf(a.y, bv.y, fg[1][1]);
        fg[1][2] = fmaf(a.y, bv.z, fg[1][2]); fg[1][3] = fmaf(a.y, bv.w, fg[1][3]);
        fg[2][0] = fmaf(a.z, bv.x, fg[2][0]); fg[2][1] = fmaf(a.z, bv.y, fg[2][1]);
        fg[2][2] = fmaf(a.z, bv.z, fg[2][2]); fg[2][3] = fmaf(a.z, bv.w, fg[2][3]);
        fg[3][0] = fmaf(a.w, bv.x, fg[3][0]); fg[3][1] = fmaf(a.w, bv.y, fg[3][1]);
        fg[3][2] = fmaf(a.w, bv.z, fg[3][2]); fg[3][3] = fmaf(a.w, bv.w, fg[3][3]);
    }
    const float c1 = LAMF * INVN;
#pragma unroll
    for (int i = 0; i < 4; i++) {
        float sneg = ss[rr + i];
        float4 gv = *(const float4*)(gin + (r0 + rr + i) * 64 + cc);
        fg[i][0] = fmaf(sneg, gv.x, c1 * fg[i][0]);
        fg[i][1] = fmaf(sneg, gv.y, c1 * fg[i][1]);
        fg[i][2] = fmaf(sneg, gv.z, c1 * fg[i][2]);
        fg[i][3] = fmaf(sneg, gv.w, c1 * fg[i][3]);
    }
    __syncthreads();   // sAt/sM fully read; reuse as sfgT

    // store fg transposed: sfgT[k=col][row]
#pragma unroll
    for (int j = 0; j < 4; j++) {
        float4 v = make_float4(fg[0][j], fg[1][j], fg[2][j], fg[3][j]);
        *(float4*)(sfgT + (cc + j) * 68 + rr) = v;
    }
    __syncthreads();

    // ---- phase 2: o = fg @ W (K=64) ----
    float acc[4][4];
#pragma unroll
    for (int i = 0; i < 4; i++)
#pragma unroll
        for (int j = 0; j < 4; j++) acc[i][j] = 0.f;

#pragma unroll 8
    for (int k = 0; k < 64; k++) {
        float4 a  = *(const float4*)(sfgT + k * 68 + rr);
        float4 bv = *(const float4*)(sW + k * 68 + cc);
        acc[0][0] = fmaf(a.x, bv.x, acc[0][0]); acc[0][1] = fmaf(a.x, bv.y, acc[0][1]);
        acc[0][2] = fmaf(a.x, bv.z, acc[0][2]); acc[0][3] = fmaf(a.x, bv.w, acc[0][3]);
        acc[1][0] = fmaf(a.y, bv.x, acc[1][0]); acc[1][1] = fmaf(a.y, bv.y, acc[1][1]);
        acc[1][2] = fmaf(a.y, bv.z, acc[1][2]); acc[1][3] = fmaf(a.y, bv.w, acc[1][3]);
        acc[2][0] = fmaf(a.z, bv.x, acc[2][0]); acc[2][1] = fmaf(a.z, bv.y, acc[2][1]);
        acc[2][2] = fmaf(a.z, bv.z, acc[2][2]); acc[2][3] = fmaf(a.z, bv.w, acc[2][3]);
        acc[3][0] = fmaf(a.w, bv.x, acc[3][0]); acc[3][1] = fmaf(a.w, bv.y, acc[3][1]);
        acc[3][2] = fmaf(a.w, bv.z, acc[3][2]); acc[3][3] = fmaf(a.w, bv.w, acc[3][3]);
    }
    if (DO_M1) __syncthreads();   // sfgT/sW dead before overlay

    // epilogue: bias, BN, ReLU, residual (last == x always)
    float4 bias = *(const float4*)(bst + ITER * 64 + cc);
    float4 gm   = *(const float4*)(gam + ITER * 64 + cc);
    float4 bt4  = *(const float4*)(bet + ITER * 64 + cc);
    float4 mmv  = *(const float4*)(mmean + ITER * 64 + cc);
    float4 mv   = *(const float4*)(mvar + ITER * 64 + cc);
    float scl[4]  = { gm.x * rsqrtf(mv.x + BNEPS), gm.y * rsqrtf(mv.y + BNEPS),
                      gm.z * rsqrtf(mv.z + BNEPS), gm.w * rsqrtf(mv.w + BNEPS) };
    float bia[4]  = { bias.x, bias.y, bias.z, bias.w };
    float mean[4] = { mmv.x, mmv.y, mmv.z, mmv.w };
    float betc[4] = { bt4.x, bt4.y, bt4.z, bt4.w };

#pragma unroll
    for (int i = 0; i < 4; i++) {
        int r = r0 + rr + i;
        float4 xv = *(const float4*)(x + r * 64 + cc);
        float xa[4] = { xv.x, xv.y, xv.z, xv.w };
        float4 ov;
        float* op = (float*)&ov;
#pragma unroll
        for (int j = 0; j < 4; j++) {
            float o = acc[i][j] + bia[j];
            o = (o - mean[j]) * scl[j] + betc[j];
            o = fmaxf(o, 0.f);
            op[j] = xa[j] + HSTEP * o;
        }
        *(float4*)(out + r * 64 + cc) = ov;
        if (DO_M1) *(float4*)(SOUT + (rr + i) * 68 + cc) = ov;
    }

    if (DO_M1) {
        // stage phi chunk [row][d]
        const float4* psrc = (const float4*)(d_phi + r0 * 32);
        ((float4*)SPHI)[t]       = psrc[t];
        ((float4*)SPHI)[t + 256] = psrc[t + 256];
        __syncthreads();

        // partial M1 = phi_chunk^T @ out_chunk
        int d2 = t & 31, cb = (t >> 5) * 8;
        float macc[8] = {0.f, 0.f, 0.f, 0.f, 0.f, 0.f, 0.f, 0.f};
#pragma unroll 8
        for (int r2 = 0; r2 < 64; r2++) {
            float pd = SPHI[r2 * 32 + d2];
            float4 o0 = *(const float4*)(SOUT + r2 * 68 + cb);
            float4 o1 = *(const float4*)(SOUT + r2 * 68 + cb + 4);
            macc[0] = fmaf(pd, o0.x, macc[0]); macc[1] = fmaf(pd, o0.y, macc[1]);
            macc[2] = fmaf(pd, o0.z, macc[2]); macc[3] = fmaf(pd, o0.w, macc[3]);
            macc[4] = fmaf(pd, o1.x, macc[4]); macc[5] = fmaf(pd, o1.y, macc[5]);
            macc[6] = fmaf(pd, o1.z, macc[6]); macc[7] = fmaf(pd, o1.w, macc[7]);
        }
        float* Mb = d_M[1] + b * 2048 + d2 * 64 + cb;
#pragma unroll
        for (int q = 0; q < 8; q++) atomicAdd(&Mb[q], macc[q]);
    }
}

// ---------------------------------------------------------------------------
extern "C" void kernel_launch(void* const* d_in, const int* in_sizes, int n_in,
                              void* d_out, int out_size) {
    const float* x     = (const float*)d_in[0];
    const float* Wt    = (const float*)d_in[1];
    const float* bt    = (const float*)d_in[2];
    const float* Wp    = (const float*)d_in[3];
    const float* bp    = (const float*)d_in[4];
    const float* Wst   = (const float*)d_in[5];
    const float* bst   = (const float*)d_in[6];
    const float* gam   = (const float*)d_in[7];
    const float* bet   = (const float*)d_in[8];
    const float* mmean = (const float*)d_in[9];
    const float* mvar  = (const float*)d_in[10];
    float* out = (float*)d_out;

    k_theta_phi<<<BNROWS / 32, 256>>>(x, Wt, bt, Wp, bp);
    k_reduceM0<<<Bb * 98, 256>>>(x);
    k_apply<0, 1><<<BNROWS / 64, 256>>>(x, Wst, bst, gam, bet, mmean, mvar, out);
    k_apply<1, 0><<<BNROWS / 64, 256>>>(x, Wst, bst, gam, bet, mmean, mvar, out);
}

// round 7
// speedup vs baseline: 1.0086x; 1.0086x over previous
#include <cuda_runtime.h>

#define Bb     8
#define Nn     3136
#define Cc     64
#define CI     32
#define BNROWS 25088          // Bb * Nn
#define LAMF   0.1f
#define HSTEP  0.05f
#define BNEPS  1e-3f
#define INVN   (1.0f / 3136.0f)

// ---- scratch (static device globals; no allocation) ----
__device__ float d_theta[BNROWS * CI];
__device__ float d_phi[BNROWS * CI];
__device__ float d_phisum[Bb * CI];
__device__ float d_pspart[784 * CI];          // per-block phi-sum partials
__device__ float d_Mpart[2][4][Bb * 2048];    // 4-way split M accum per iter
__device__ float d_g1[BNROWS * Cc];

// ===========================================================================
// K1: theta/phi = x @ Wt/Wp + bias; per-block phi-sum partials; blocks 0-127
// zero all M partial buffers (this kernel never touches them otherwise).
__global__ void __launch_bounds__(256) k_theta_phi(
        const float* __restrict__ x,
        const float* __restrict__ Wt, const float* __restrict__ bt,
        const float* __restrict__ Wp, const float* __restrict__ bp) {
    __shared__ float sx[32 * 64];
    __shared__ float sWt[32 * 68];
    __shared__ float sWp[32 * 68];
    __shared__ float sp[32];
    int t  = threadIdx.x;
    int gb = blockIdx.x;
    int r0 = gb * 32;

    if (gb < 128) {   // zero M partials: 2*4*8*2048 floats = 32768 float4
        float4 z = make_float4(0.f, 0.f, 0.f, 0.f);
        ((float4*)d_Mpart)[gb * 256 + t] = z;
    }
    {
        const float4* src = (const float4*)(x + r0 * 64);
        ((float4*)sx)[t]       = src[t];
        ((float4*)sx)[t + 256] = src[t + 256];
    }
    for (int e = t; e < 2048; e += 256) {   // weights transposed
        int k = e >> 5, d = e & 31;
        sWt[d * 68 + k] = Wt[e];
        sWp[d * 68 + k] = Wp[e];
    }
    if (t < 32) sp[t] = 0.f;
    __syncthreads();

    int w = t >> 5, d = t & 31;
    float th[4], ph[4];
    float bt_d = bt[d], bp_d = bp[d];
#pragma unroll
    for (int j = 0; j < 4; j++) { th[j] = bt_d; ph[j] = bp_d; }

    const float* xr = sx + w * 4 * 64;
    const float* wt = sWt + d * 68;
    const float* wp = sWp + d * 68;
#pragma unroll
    for (int k = 0; k < 64; k += 4) {
        float4 a = *(const float4*)(wt + k);
        float4 b = *(const float4*)(wp + k);
#pragma unroll
        for (int j = 0; j < 4; j++) {
            float4 xv = *(const float4*)(xr + j * 64 + k);
            th[j] = fmaf(xv.x, a.x, th[j]); th[j] = fmaf(xv.y, a.y, th[j]);
            th[j] = fmaf(xv.z, a.z, th[j]); th[j] = fmaf(xv.w, a.w, th[j]);
            ph[j] = fmaf(xv.x, b.x, ph[j]); ph[j] = fmaf(xv.y, b.y, ph[j]);
            ph[j] = fmaf(xv.z, b.z, ph[j]); ph[j] = fmaf(xv.w, b.w, ph[j]);
        }
    }
    int r = r0 + w * 4;
    float phs = 0.f;
#pragma unroll
    for (int j = 0; j < 4; j++) {
        d_theta[(r + j) * 32 + d] = th[j];
        d_phi[(r + j) * 32 + d]   = ph[j];
        phs += ph[j];
    }
    atomicAdd(&sp[d], phs);
    __syncthreads();
    if (t < 32) d_pspart[gb * 32 + t] = sp[t];
}

// ===========================================================================
// K2/K4: Mpart[iter][s][b] += phi^T @ g over 32-row chunks. grid 784 (98/batch).
// Lane layout d = t>>3, c0 = (t&7)*8 -> warp REDG covers 4 contiguous rows.
// ITER==0 chunk-0 blocks finalize d_phisum (idempotent).
template<int ITER>
__global__ void __launch_bounds__(256) k_reduceM(const float* __restrict__ x) {
    const float* g = ITER ? d_g1 : x;
    __shared__ float sph[32 * 32];
    __shared__ float sg[32 * 64];
    int t     = threadIdx.x;
    int b     = blockIdx.x / 98;
    int chunk = blockIdx.x % 98;
    int s     = chunk & 3;
    int row0  = b * Nn + chunk * 32;

    if (ITER == 0 && chunk == 0 && t < 32) {
        float a = 0.f;
        for (int j = 0; j < 98; j++) a += d_pspart[(b * 98 + j) * 32 + t];
        d_phisum[b * 32 + t] = a;
    }

    ((float4*)sph)[t] = ((const float4*)(d_phi + row0 * 32))[t];
    {
        const float4* src = (const float4*)(g + row0 * 64);
        ((float4*)sg)[t]       = src[t];
        ((float4*)sg)[t + 256] = src[t + 256];
    }
    __syncthreads();

    int d  = t >> 3;          // 0..31
    int c0 = (t & 7) * 8;     // 0..56
    float acc[8] = {0.f, 0.f, 0.f, 0.f, 0.f, 0.f, 0.f, 0.f};
#pragma unroll 8
    for (int r = 0; r < 32; r++) {
        float pd = sph[r * 32 + d];
        float4 g0  = *(const float4*)(sg + r * 64 + c0);
        float4 g1v = *(const float4*)(sg + r * 64 + c0 + 4);
        acc[0] = fmaf(pd, g0.x, acc[0]);  acc[1] = fmaf(pd, g0.y, acc[1]);
        acc[2] = fmaf(pd, g0.z, acc[2]);  acc[3] = fmaf(pd, g0.w, acc[3]);
        acc[4] = fmaf(pd, g1v.x, acc[4]); acc[5] = fmaf(pd, g1v.y, acc[5]);
        acc[6] = fmaf(pd, g1v.z, acc[6]); acc[7] = fmaf(pd, g1v.w, acc[7]);
    }
    float* Mb = d_Mpart[ITER][s] + b * 2048 + d * 64 + c0;
#pragma unroll
    for (int q = 0; q < 8; q++) atomicAdd(&Mb[q], acc[q]);
}

// ===========================================================================
// K3/K5: two-phase apply (R5-proven).
//   phase1: raw = theta @ M (K=32); fg = (lam/N)*raw - (s/N)*g
//   phase2: o = fg @ W + bias; BN; ReLU; out = x + 0.05*o
// M staged by summing the 4 partial buffers.
template<int ITER>
__global__ void __launch_bounds__(256) k_apply(
        const float* __restrict__ x,
        const float* __restrict__ Wst, const float* __restrict__ bst,
        const float* __restrict__ gam, const float* __restrict__ bet,
        const float* __restrict__ mmean, const float* __restrict__ mvar,
        float* __restrict__ out_ext) {
    const float* gin = ITER ? d_g1 : x;
    float* out       = ITER ? out_ext : d_g1;

    __shared__ float sm[8800];
    float* sAt  = sm;          // theta^T [k=32][row 64] pad 68   (2176)
    float* sM   = sm + 2176;   // M [k=32][col 64] pad 68          (2176)
    float* sW   = sm + 4352;   // W [k=64][col 64] pad 68          (4352)
    float* sfgT = sm;          // fg^T [k=64][row 64] pad 68, overlays sAt+sM
    float* ss   = sm + 8704;   // 64
    float* sps  = sm + 8768;   // 32

    int t  = threadIdx.x;
    int r0 = blockIdx.x * 64;
    int b  = blockIdx.x / 49;

    // stage theta^T
#pragma unroll
    for (int j = 0; j < 2; j++) {
        int e = t + j * 256;
        int r = e >> 3, dd = (e & 7) * 4;
        float4 v = ((const float4*)(d_theta + r0 * 32))[e];
        sAt[(dd + 0) * 68 + r] = v.x;
        sAt[(dd + 1) * 68 + r] = v.y;
        sAt[(dd + 2) * 68 + r] = v.z;
        sAt[(dd + 3) * 68 + r] = v.w;
    }
    // stage M = sum of 4 partial buffers
    {
        const float4* P0 = (const float4*)(d_Mpart[ITER][0] + b * 2048);
        const float4* P1 = (const float4*)(d_Mpart[ITER][1] + b * 2048);
        const float4* P2 = (const float4*)(d_Mpart[ITER][2] + b * 2048);
        const float4* P3 = (const float4*)(d_Mpart[ITER][3] + b * 2048);
#pragma unroll
        for (int j = 0; j < 2; j++) {
            int e = t + j * 256;
            int k = e >> 4, c4 = (e & 15) * 4;
            float4 a0 = P0[e], a1 = P1[e], a2 = P2[e], a3 = P3[e];
            float4 v;
            v.x = (a0.x + a1.x) + (a2.x + a3.x);
            v.y = (a0.y + a1.y) + (a2.y + a3.y);
            v.z = (a0.z + a1.z) + (a2.z + a3.z);
            v.w = (a0.w + a1.w) + (a2.w + a3.w);
            *(float4*)(sM + k * 68 + c4) = v;
        }
    }
    // stage W
    const float* Wi = Wst + ITER * 4096;
#pragma unroll
    for (int j = 0; j < 4; j++) {
        int e = t + j * 256;
        int k = e >> 4, c4 = (e & 15) * 4;
        *(float4*)(sW + k * 68 + c4) = ((const float4*)Wi)[e];
    }
    if (t < 32) sps[t] = d_phisum[b * 32 + t];
    __syncthreads();

    if (t < 64) {   // -(s/N) per row, s = LAM * theta . phisum
        float a = 0.f;
#pragma unroll
        for (int k = 0; k < 32; k++) a = fmaf(sAt[k * 68 + t], sps[k], a);
        ss[t] = a * (-LAMF * INVN);
    }
    __syncthreads();

    int tx = t & 15, ty = t >> 4;
    int rr = ty * 4, cc = tx * 4;

    // ---- phase 1: raw = theta @ M (K=32) ----
    float fg[4][4];
#pragma unroll
    for (int i = 0; i < 4; i++)
#pragma unroll
        for (int j = 0; j < 4; j++) fg[i][j] = 0.f;

#pragma unroll 8
    for (int k = 0; k < 32; k++) {
        float4 a  = *(const float4*)(sAt + k * 68 + rr);
        float4 bv = *(const float4*)(sM + k * 68 + cc);
        fg[0][0] = fmaf(a.x, bv.x, fg[0][0]); fg[0][1] = fmaf(a.x, bv.y, fg[0][1]);
        fg[0][2] = fmaf(a.x, bv.z, fg[0][2]); fg[0][3] = fmaf(a.x, bv.w, fg[0][3]);
        fg[1][0] = fmaf(a.y, bv.x, fg[1][0]); fg[1][1] = fmaf(a.y, bv.y, fg[1][1]);
        fg[1][2] = fmaf(a.y, bv.z, fg[1][2]); fg[1][3] = fmaf(a.y, bv.w, fg[1][3]);
        fg[2][0] = fmaf(a.z, bv.x, fg[2][0]); fg[2][1] = fmaf(a.z, bv.y, fg[2][1]);
        fg[2][2] = fmaf(a.z, bv.z, fg[2][2]); fg[2][3] = fmaf(a.z, bv.w, fg[2][3]);
        fg[3][0] = fmaf(a.w, bv.x, fg[3][0]); fg[3][1] = fmaf(a.w, bv.y, fg[3][1]);
        fg[3][2] = fmaf(a.w, bv.z, fg[3][2]); fg[3][3] = fmaf(a.w, bv.w, fg[3][3]);
    }
    const float c1 = LAMF * INVN;
#pragma unroll
    for (int i = 0; i < 4; i++) {
        float sneg = ss[rr + i];
        float4 gv = *(const float4*)(gin + (r0 + rr + i) * 64 + cc);
        fg[i][0] = fmaf(sneg, gv.x, c1 * fg[i][0]);
        fg[i][1] = fmaf(sneg, gv.y, c1 * fg[i][1]);
        fg[i][2] = fmaf(sneg, gv.z, c1 * fg[i][2]);
        fg[i][3] = fmaf(sneg, gv.w, c1 * fg[i][3]);
    }
    __syncthreads();   // sAt/sM fully read; reuse as sfgT

    // store fg transposed: sfgT[k=col][row]
#pragma unroll
    for (int j = 0; j < 4; j++) {
        float4 v = make_float4(fg[0][j], fg[1][j], fg[2][j], fg[3][j]);
        *(float4*)(sfgT + (cc + j) * 68 + rr) = v;
    }
    __syncthreads();

    // ---- phase 2: o = fg @ W (K=64) ----
    float acc[4][4];
#pragma unroll
    for (int i = 0; i < 4; i++)
#pragma unroll
        for (int j = 0; j < 4; j++) acc[i][j] = 0.f;

#pragma unroll 8
    for (int k = 0; k < 64; k++) {
        float4 a  = *(const float4*)(sfgT + k * 68 + rr);
        float4 bv = *(const float4*)(sW + k * 68 + cc);
        acc[0][0] = fmaf(a.x, bv.x, acc[0][0]); acc[0][1] = fmaf(a.x, bv.y, acc[0][1]);
        acc[0][2] = fmaf(a.x, bv.z, acc[0][2]); acc[0][3] = fmaf(a.x, bv.w, acc[0][3]);
        acc[1][0] = fmaf(a.y, bv.x, acc[1][0]); acc[1][1] = fmaf(a.y, bv.y, acc[1][1]);
        acc[1][2] = fmaf(a.y, bv.z, acc[1][2]); acc[1][3] = fmaf(a.y, bv.w, acc[1][3]);
        acc[2][0] = fmaf(a.z, bv.x, acc[2][0]); acc[2][1] = fmaf(a.z, bv.y, acc[2][1]);
        acc[2][2] = fmaf(a.z, bv.z, acc[2][2]); acc[2][3] = fmaf(a.z, bv.w, acc[2][3]);
        acc[3][0] = fmaf(a.w, bv.x, acc[3][0]); acc[3][1] = fmaf(a.w, bv.y, acc[3][1]);
        acc[3][2] = fmaf(a.w, bv.z, acc[3][2]); acc[3][3] = fmaf(a.w, bv.w, acc[3][3]);
    }

    // epilogue: bias, BN, ReLU, residual (last == x always)
    float4 bias = *(const float4*)(bst + ITER * 64 + cc);
    float4 gm   = *(const float4*)(gam + ITER * 64 + cc);
    float4 bt4  = *(const float4*)(bet + ITER * 64 + cc);
    float4 mmv  = *(const float4*)(mmean + ITER * 64 + cc);
    float4 mv   = *(const float4*)(mvar + ITER * 64 + cc);
    float scl[4]  = { gm.x * rsqrtf(mv.x + BNEPS), gm.y * rsqrtf(mv.y + BNEPS),
                      gm.z * rsqrtf(mv.z + BNEPS), gm.w * rsqrtf(mv.w + BNEPS) };
    float bia[4]  = { bias.x, bias.y, bias.z, bias.w };
    float mean[4] = { mmv.x, mmv.y, mmv.z, mmv.w };
    float betc[4] = { bt4.x, bt4.y, bt4.z, bt4.w };

#pragma unroll
    for (int i = 0; i < 4; i++) {
        int r = r0 + rr + i;
        float4 xv = *(const float4*)(x + r * 64 + cc);
        float xa[4] = { xv.x, xv.y, xv.z, xv.w };
        float4 ov;
        float* op = (float*)&ov;
#pragma unroll
        for (int j = 0; j < 4; j++) {
            float o = acc[i][j] + bia[j];
            o = (o - mean[j]) * scl[j] + betc[j];
            o = fmaxf(o, 0.f);
            op[j] = xa[j] + HSTEP * o;
        }
        *(float4*)(out + r * 64 + cc) = ov;
    }
}

// ---------------------------------------------------------------------------
extern "C" void kernel_launch(void* const* d_in, const int* in_sizes, int n_in,
                              void* d_out, int out_size) {
    const float* x     = (const float*)d_in[0];
    const float* Wt    = (const float*)d_in[1];
    const float* bt    = (const float*)d_in[2];
    const float* Wp    = (const float*)d_in[3];
    const float* bp    = (const float*)d_in[4];
    const float* Wst   = (const float*)d_in[5];
    const float* bst   = (const float*)d_in[6];
    const float* gam   = (const float*)d_in[7];
    const float* bet   = (const float*)d_in[8];
    const float* mmean = (const float*)d_in[9];
    const float* mvar  = (const float*)d_in[10];
    float* out = (float*)d_out;

    k_theta_phi<<<BNROWS / 32, 256>>>(x, Wt, bt, Wp, bp);
    k_reduceM<0><<<Bb * 98, 256>>>(x);
    k_apply<0><<<BNROWS / 64, 256>>>(x, Wst, bst, gam, bet, mmean, mvar, out);
    k_reduceM<1><<<Bb * 98, 256>>>(x);
    k_apply<1><<<BNROWS / 64, 256>>>(x, Wst, bst, gam, bet, mmean, mvar, out);
}

// round 8
// speedup vs baseline: 1.1984x; 1.1882x over previous
#include <cuda_runtime.h>

#define Bb     8
#define Nn     3136
#define Cc     64
#define CI     32
#define BNROWS 25088          // Bb * Nn
#define LAMF   0.1f
#define HSTEP  0.05f
#define BNEPS  1e-3f
#define INVN   (1.0f / 3136.0f)

// ---- scratch (static device globals; no allocation) ----
__device__ float d_theta[BNROWS * CI];
__device__ float d_phi[BNROWS * CI];
__device__ float d_phisum[Bb * CI];
__device__ float d_pspart[784 * CI];     // per-block phi-sum partials
__device__ float d_M[2][Bb * 2048];      // phi^T g per iter; zeroed in k_theta_phi
__device__ float d_g1[BNROWS * Cc];

__device__ __forceinline__ void redg_v4(float* p, float a, float b, float c, float d) {
    asm volatile("red.global.add.v4.f32 [%0], {%1, %2, %3, %4};"
                 :: "l"(p), "f"(a), "f"(b), "f"(c), "f"(d) : "memory");
}

// ===========================================================================
// K1: theta/phi = x @ Wt/Wp + bias; per-block phi-sum partials; blocks 0-31
// zero both d_M buffers (this kernel never touches d_M otherwise).
__global__ void __launch_bounds__(256) k_theta_phi(
        const float* __restrict__ x,
        const float* __restrict__ Wt, const float* __restrict__ bt,
        const float* __restrict__ Wp, const float* __restrict__ bp) {
    __shared__ float sx[32 * 64];
    __shared__ float sWt[32 * 68];
    __shared__ float sWp[32 * 68];
    __shared__ float sp[32];
    int t  = threadIdx.x;
    int gb = blockIdx.x;
    int r0 = gb * 32;

    if (gb < 32) {   // zero both M buffers: 8192 float4 total
        float4 z = make_float4(0.f, 0.f, 0.f, 0.f);
        ((float4*)d_M)[gb * 256 + t] = z;
    }
    {
        const float4* src = (const float4*)(x + r0 * 64);
        ((float4*)sx)[t]       = src[t];
        ((float4*)sx)[t + 256] = src[t + 256];
    }
    for (int e = t; e < 2048; e += 256) {   // weights transposed
        int k = e >> 5, d = e & 31;
        sWt[d * 68 + k] = Wt[e];
        sWp[d * 68 + k] = Wp[e];
    }
    if (t < 32) sp[t] = 0.f;
    __syncthreads();

    int w = t >> 5, d = t & 31;
    float th[4], ph[4];
    float bt_d = bt[d], bp_d = bp[d];
#pragma unroll
    for (int j = 0; j < 4; j++) { th[j] = bt_d; ph[j] = bp_d; }

    const float* xr = sx + w * 4 * 64;
    const float* wt = sWt + d * 68;
    const float* wp = sWp + d * 68;
#pragma unroll
    for (int k = 0; k < 64; k += 4) {
        float4 a = *(const float4*)(wt + k);
        float4 b = *(const float4*)(wp + k);
#pragma unroll
        for (int j = 0; j < 4; j++) {
            float4 xv = *(const float4*)(xr + j * 64 + k);
            th[j] = fmaf(xv.x, a.x, th[j]); th[j] = fmaf(xv.y, a.y, th[j]);
            th[j] = fmaf(xv.z, a.z, th[j]); th[j] = fmaf(xv.w, a.w, th[j]);
            ph[j] = fmaf(xv.x, b.x, ph[j]); ph[j] = fmaf(xv.y, b.y, ph[j]);
            ph[j] = fmaf(xv.z, b.z, ph[j]); ph[j] = fmaf(xv.w, b.w, ph[j]);
        }
    }
    int r = r0 + w * 4;
    float phs = 0.f;
#pragma unroll
    for (int j = 0; j < 4; j++) {
        d_theta[(r + j) * 32 + d] = th[j];
        d_phi[(r + j) * 32 + d]   = ph[j];
        phs += ph[j];
    }
    atomicAdd(&sp[d], phs);
    __syncthreads();
    if (t < 32) d_pspart[gb * 32 + t] = sp[t];
}

// ===========================================================================
// K2/K4: M[iter][b] += phi[b]^T @ g[b]. 64 rows/block, 4 double-buffered
// 16-row tiles (R5-proven). Lane layout d=t>>3, c0=(t&7)*8 so each warp's
// REDG covers 4 contiguous rows; emission via 2x red.global.add.v4.f32.
// ITER==0 chunk-0 blocks finalize d_phisum (idempotent).
template<int ITER>
__global__ void __launch_bounds__(256) k_reduceM(const float* __restrict__ x) {
    const float* g = ITER ? d_g1 : x;
    __shared__ float sph[2][16 * 32];
    __shared__ float sg[2][16 * 64];
    int t     = threadIdx.x;
    int b     = blockIdx.x / 49;
    int chunk = blockIdx.x % 49;
    int row0  = b * Nn + chunk * 64;

    if (ITER == 0 && chunk == 0 && t < 32) {
        float a = 0.f;
        for (int j = 0; j < 98; j++) a += d_pspart[(b * 98 + j) * 32 + t];
        d_phisum[b * 32 + t] = a;
    }

    int d = t >> 3, c0 = (t & 7) * 8;
    float acc[8] = {0.f, 0.f, 0.f, 0.f, 0.f, 0.f, 0.f, 0.f};

    const float4* phg = (const float4*)(d_phi + row0 * 32);
    const float4* gg  = (const float4*)(g + row0 * 64);

    if (t < 128) ((float4*)sph[0])[t] = phg[t];
    ((float4*)sg[0])[t] = gg[t];
    __syncthreads();

#pragma unroll
    for (int tt = 0; tt < 4; tt++) {
        int cur = tt & 1, nxt = cur ^ 1;
        float4 pre_p, pre_g;
        if (tt < 3) {
            if (t < 128) pre_p = phg[(tt + 1) * 128 + t];
            pre_g = gg[(tt + 1) * 256 + t];
        }
        const float* P = sph[cur];
        const float* G = sg[cur];
#pragma unroll
        for (int j = 0; j < 16; j++) {
            float pd = P[j * 32 + d];
            float4 g0  = *(const float4*)(G + j * 64 + c0);
            float4 g1v = *(const float4*)(G + j * 64 + c0 + 4);
            acc[0] = fmaf(pd, g0.x, acc[0]);  acc[1] = fmaf(pd, g0.y, acc[1]);
            acc[2] = fmaf(pd, g0.z, acc[2]);  acc[3] = fmaf(pd, g0.w, acc[3]);
            acc[4] = fmaf(pd, g1v.x, acc[4]); acc[5] = fmaf(pd, g1v.y, acc[5]);
            acc[6] = fmaf(pd, g1v.z, acc[6]); acc[7] = fmaf(pd, g1v.w, acc[7]);
        }
        if (tt < 3) {
            if (t < 128) ((float4*)sph[nxt])[t] = pre_p;
            ((float4*)sg[nxt])[t] = pre_g;
        }
        __syncthreads();
    }
    float* Mb = d_M[ITER] + b * 2048 + d * 64 + c0;
    redg_v4(Mb,     acc[0], acc[1], acc[2], acc[3]);
    redg_v4(Mb + 4, acc[4], acc[5], acc[6], acc[7]);
}

// ===========================================================================
// K3/K5: two-phase apply (R5-proven, unchanged).
//   phase1: raw = theta @ M (K=32); fg = (lam/N)*raw - (s/N)*g
//   phase2: o = fg @ W + bias; BN; ReLU; out = x + 0.05*o
template<int ITER>
__global__ void __launch_bounds__(256) k_apply(
        const float* __restrict__ x,
        const float* __restrict__ Wst, const float* __restrict__ bst,
        const float* __restrict__ gam, const float* __restrict__ bet,
        const float* __restrict__ mmean, const float* __restrict__ mvar,
        float* __restrict__ out_ext) {
    const float* gin = ITER ? d_g1 : x;
    float* out       = ITER ? out_ext : d_g1;

    __shared__ float sm[8800];
    float* sAt  = sm;          // theta^T [k=32][row 64] pad 68   (2176)
    float* sM   = sm + 2176;   // M [k=32][col 64] pad 68          (2176)
    float* sW   = sm + 4352;   // W [k=64][col 64] pad 68          (4352)
    float* sfgT = sm;          // fg^T [k=64][row 64] pad 68, overlays sAt+sM
    float* ss   = sm + 8704;   // 64
    float* sps  = sm + 8768;   // 32

    int t  = threadIdx.x;
    int r0 = blockIdx.x * 64;
    int b  = blockIdx.x / 49;

    // stage theta^T
#pragma unroll
    for (int j = 0; j < 2; j++) {
        int e = t + j * 256;
        int r = e >> 3, dd = (e & 7) * 4;
        float4 v = ((const float4*)(d_theta + r0 * 32))[e];
        sAt[(dd + 0) * 68 + r] = v.x;
        sAt[(dd + 1) * 68 + r] = v.y;
        sAt[(dd + 2) * 68 + r] = v.z;
        sAt[(dd + 3) * 68 + r] = v.w;
    }
    // stage M
    const float* Mi = d_M[ITER] + b * 2048;
#pragma unroll
    for (int j = 0; j < 2; j++) {
        int e = t + j * 256;
        int k = e >> 4, c4 = (e & 15) * 4;
        *(float4*)(sM + k * 68 + c4) = ((const float4*)Mi)[e];
    }
    // stage W
    const float* Wi = Wst + ITER * 4096;
#pragma unroll
    for (int j = 0; j < 4; j++) {
        int e = t + j * 256;
        int k = e >> 4, c4 = (e & 15) * 4;
        *(float4*)(sW + k * 68 + c4) = ((const float4*)Wi)[e];
    }
    if (t < 32) sps[t] = d_phisum[b * 32 + t];
    __syncthreads();

    if (t < 64) {   // -(s/N) per row, s = LAM * theta . phisum
        float a = 0.f;
#pragma unroll
        for (int k = 0; k < 32; k++) a = fmaf(sAt[k * 68 + t], sps[k], a);
        ss[t] = a * (-LAMF * INVN);
    }
    __syncthreads();

    int tx = t & 15, ty = t >> 4;
    int rr = ty * 4, cc = tx * 4;

    // ---- phase 1: raw = theta @ M (K=32) ----
    float fg[4][4];
#pragma unroll
    for (int i = 0; i < 4; i++)
#pragma unroll
        for (int j = 0; j < 4; j++) fg[i][j] = 0.f;

#pragma unroll 8
    for (int k = 0; k < 32; k++) {
        float4 a  = *(const float4*)(sAt + k * 68 + rr);
        float4 bv = *(const float4*)(sM + k * 68 + cc);
        fg[0][0] = fmaf(a.x, bv.x, fg[0][0]); fg[0][1] = fmaf(a.x, bv.y, fg[0][1]);
        fg[0][2] = fmaf(a.x, bv.z, fg[0][2]); fg[0][3] = fmaf(a.x, bv.w, fg[0][3]);
        fg[1][0] = fmaf(a.y, bv.x, fg[1][0]); fg[1][1] = fmaf(a.y, bv.y, fg[1][1]);
        fg[1][2] = fmaf(a.y, bv.z, fg[1][2]); fg[1][3] = fmaf(a.y, bv.w, fg[1][3]);
        fg[2][0] = fmaf(a.z, bv.x, fg[2][0]); fg[2][1] = fmaf(a.z, bv.y, fg[2][1]);
        fg[2][2] = fmaf(a.z, bv.z, fg[2][2]); fg[2][3] = fmaf(a.z, bv.w, fg[2][3]);
        fg[3][0] = fmaf(a.w, bv.x, fg[3][0]); fg[3][1] = fmaf(a.w, bv.y, fg[3][1]);
        fg[3][2] = fmaf(a.w, bv.z, fg[3][2]); fg[3][3] = fmaf(a.w, bv.w, fg[3][3]);
    }
    const float c1 = LAMF * INVN;
#pragma unroll
    for (int i = 0; i < 4; i++) {
        float sneg = ss[rr + i];
        float4 gv = *(const float4*)(gin + (r0 + rr + i) * 64 + cc);
        fg[i][0] = fmaf(sneg, gv.x, c1 * fg[i][0]);
        fg[i][1] = fmaf(sneg, gv.y, c1 * fg[i][1]);
        fg[i][2] = fmaf(sneg, gv.z, c1 * fg[i][2]);
        fg[i][3] = fmaf(sneg, gv.w, c1 * fg[i][3]);
    }
    __syncthreads();   // sAt/sM fully read; reuse as sfgT

    // store fg transposed: sfgT[k=col][row]
#pragma unroll
    for (int j = 0; j < 4; j++) {
        float4 v = make_float4(fg[0][j], fg[1][j], fg[2][j], fg[3][j]);
        *(float4*)(sfgT + (cc + j) * 68 + rr) = v;
    }
    __syncthreads();

    // ---- phase 2: o = fg @ W (K=64) ----
    float acc[4][4];
#pragma unroll
    for (int i = 0; i < 4; i++)
#pragma unroll
        for (int j = 0; j < 4; j++) acc[i][j] = 0.f;

#pragma unroll 8
    for (int k = 0; k < 64; k++) {
        float4 a  = *(const float4*)(sfgT + k * 68 + rr);
        float4 bv = *(const float4*)(sW + k * 68 + cc);
        acc[0][0] = fmaf(a.x, bv.x, acc[0][0]); acc[0][1] = fmaf(a.x, bv.y, acc[0][1]);
        acc[0][2] = fmaf(a.x, bv.z, acc[0][2]); acc[0][3] = fmaf(a.x, bv.w, acc[0][3]);
        acc[1][0] = fmaf(a.y, bv.x, acc[1][0]); acc[1][1] = fmaf(a.y, bv.y, acc[1][1]);
        acc[1][2] = fmaf(a.y, bv.z, acc[1][2]); acc[1][3] = fmaf(a.y, bv.w, acc[1][3]);
        acc[2][0] = fmaf(a.z, bv.x, acc[2][0]); acc[2][1] = fmaf(a.z, bv.y, acc[2][1]);
        acc[2][2] = fmaf(a.z, bv.z, acc[2][2]); acc[2][3] = fmaf(a.z, bv.w, acc[2][3]);
        acc[3][0] = fmaf(a.w, bv.x, acc[3][0]); acc[3][1] = fmaf(a.w, bv.y, acc[3][1]);
        acc[3][2] = fmaf(a.w, bv.z, acc[3][2]); acc[3][3] = fmaf(a.w, bv.w, acc[3][3]);
    }

    // epilogue: bias, BN, ReLU, residual (last == x always)
    float4 bias = *(const float4*)(bst + ITER * 64 + cc);
    float4 gm   = *(const float4*)(gam + ITER * 64 + cc);
    float4 bt4  = *(const float4*)(bet + ITER * 64 + cc);
    float4 mmv  = *(const float4*)(mmean + ITER * 64 + cc);
    float4 mv   = *(const float4*)(mvar + ITER * 64 + cc);
    float scl[4]  = { gm.x * rsqrtf(mv.x + BNEPS), gm.y * rsqrtf(mv.y + BNEPS),
                      gm.z * rsqrtf(mv.z + BNEPS), gm.w * rsqrtf(mv.w + BNEPS) };
    float bia[4]  = { bias.x, bias.y, bias.z, bias.w };
    float mean[4] = { mmv.x, mmv.y, mmv.z, mmv.w };
    float betc[4] = { bt4.x, bt4.y, bt4.z, bt4.w };

#pragma unroll
    for (int i = 0; i < 4; i++) {
        int r = r0 + rr + i;
        float4 xv = *(const float4*)(x + r * 64 + cc);
        float xa[4] = { xv.x, xv.y, xv.z, xv.w };
        float4 ov;
        float* op = (float*)&ov;
#pragma unroll
        for (int j = 0; j < 4; j++) {
            float o = acc[i][j] + bia[j];
            o = (o - mean[j]) * scl[j] + betc[j];
            o = fmaxf(o, 0.f);
            op[j] = xa[j] + HSTEP * o;
        }
        *(float4*)(out + r * 64 + cc) = ov;
    }
}

// ---------------------------------------------------------------------------
extern "C" void kernel_launch(void* const* d_in, const int* in_sizes, int n_in,
                              void* d_out, int out_size) {
    const float* x     = (const float*)d_in[0];
    const float* Wt    = (const float*)d_in[1];
    const float* bt    = (const float*)d_in[2];
    const float* Wp    = (const float*)d_in[3];
    const float* bp    = (const float*)d_in[4];
    const float* Wst   = (const float*)d_in[5];
    const float* bst   = (const float*)d_in[6];
    const float* gam   = (const float*)d_in[7];
    const float* bet   = (const float*)d_in[8];
    const float* mmean = (const float*)d_in[9];
    const float* mvar  = (const float*)d_in[10];
    float* out = (float*)d_out;

    k_theta_phi<<<BNROWS / 32, 256>>>(x, Wt, bt, Wp, bp);
    k_reduceM<0><<<Bb * 49, 256>>>(x);
    k_apply<0><<<BNROWS / 64, 256>>>(x, Wst, bst, gam, bet, mmean, mvar, out);
    k_reduceM<1><<<Bb * 49, 256>>>(x);
    k_apply<1><<<BNROWS / 64, 256>>>(x, Wst, bst, gam, bet, mmean, mvar, out);
}

// round 10
// speedup vs baseline: 1.6279x; 1.3583x over previous
#include <cuda_runtime.h>

#define Bb     8
#define Nn     3136
#define Cc     64
#define CI     32
#define BNROWS 25088          // Bb * Nn
#define LAMF   0.1f
#define HSTEP  0.05f
#define BNEPS  1e-3f
#define INVN   (1.0f / 3136.0f)

// ---- scratch (static device globals; no allocation) ----
__device__ float d_theta[BNROWS * CI];
__device__ float d_phi[BNROWS * CI];
__device__ float d_phisum[Bb * CI];
__device__ float d_pspart[784 * CI];     // per-block phi-sum partials
__device__ float d_M[2][Bb * 2048];      // phi^T g per iter; zeroed in k_theta_phi
__device__ float d_g1[BNROWS * Cc];

__device__ __forceinline__ void redg_v4(float* p, float a, float b, float c, float d) {
    asm volatile("red.global.add.v4.f32 [%0], {%1, %2, %3, %4};"
                 :: "l"(p), "f"(a), "f"(b), "f"(c), "f"(d) : "memory");
}

// ===========================================================================
// K1: theta/phi = x @ Wt/Wp + bias; per-block phi-sum partials; blocks 0-31
// zero both d_M buffers (this kernel never touches d_M otherwise).
__global__ void __launch_bounds__(256) k_theta_phi(
        const float* __restrict__ x,
        const float* __restrict__ Wt, const float* __restrict__ bt,
        const float* __restrict__ Wp, const float* __restrict__ bp) {
    __shared__ float sx[32 * 64];
    __shared__ float sWt[32 * 68];
    __shared__ float sWp[32 * 68];
    __shared__ float sp[32];
    int t  = threadIdx.x;
    int gb = blockIdx.x;
    int r0 = gb * 32;

    if (gb < 32) {   // zero both M buffers: 8192 float4 total
        float4 z = make_float4(0.f, 0.f, 0.f, 0.f);
        ((float4*)d_M)[gb * 256 + t] = z;
    }
    {
        const float4* src = (const float4*)(x + r0 * 64);
        ((float4*)sx)[t]       = src[t];
        ((float4*)sx)[t + 256] = src[t + 256];
    }
    for (int e = t; e < 2048; e += 256) {   // weights transposed
        int k = e >> 5, d = e & 31;
        sWt[d * 68 + k] = Wt[e];
        sWp[d * 68 + k] = Wp[e];
    }
    if (t < 32) sp[t] = 0.f;
    __syncthreads();

    int w = t >> 5, d = t & 31;
    float th[4], ph[4];
    float bt_d = bt[d], bp_d = bp[d];
#pragma unroll
    for (int j = 0; j < 4; j++) { th[j] = bt_d; ph[j] = bp_d; }

    const float* xr = sx + w * 4 * 64;
    const float* wt = sWt + d * 68;
    const float* wp = sWp + d * 68;
#pragma unroll
    for (int k = 0; k < 64; k += 4) {
        float4 a = *(const float4*)(wt + k);
        float4 b = *(const float4*)(wp + k);
#pragma unroll
        for (int j = 0; j < 4; j++) {
            float4 xv = *(const float4*)(xr + j * 64 + k);
            th[j] = fmaf(xv.x, a.x, th[j]); th[j] = fmaf(xv.y, a.y, th[j]);
            th[j] = fmaf(xv.z, a.z, th[j]); th[j] = fmaf(xv.w, a.w, th[j]);
            ph[j] = fmaf(xv.x, b.x, ph[j]); ph[j] = fmaf(xv.y, b.y, ph[j]);
            ph[j] = fmaf(xv.z, b.z, ph[j]); ph[j] = fmaf(xv.w, b.w, ph[j]);
        }
    }
    int r = r0 + w * 4;
    float phs = 0.f;
#pragma unroll
    for (int j = 0; j < 4; j++) {
        d_theta[(r + j) * 32 + d] = th[j];
        d_phi[(r + j) * 32 + d]   = ph[j];
        phs += ph[j];
    }
    atomicAdd(&sp[d], phs);
    __syncthreads();
    if (t < 32) d_pspart[gb * 32 + t] = sp[t];
}

// ===========================================================================
// K2/K4: M[iter][b] += phi[b]^T @ g[b]. 64 rows/block, grid 392.
// 4x4 register tile: 256 threads = 2 row-groups x (8 d-tiles x 16 c-tiles);
// per row: 2 LDS.128 -> 16 FMA. Row-group partials reduced via smem, then
// 2x red.global.add.v4.f32 per thread (identical emission to R8).
// ITER==0 chunk-0 blocks finalize d_phisum (idempotent).
template<int ITER>
__global__ void __launch_bounds__(256) k_reduceM(const float* __restrict__ x) {
    const float* g = ITER ? d_g1 : x;
    __shared__ float sm[6144];              // 24 KB
    float* sph = sm;                        // [64][32]
    float* sg  = sm + 2048;                 // [64][64]
    // partials overlay (after compute): [2][32][68] at sm[0..4352)

    int t     = threadIdx.x;
    int b     = blockIdx.x / 49;
    int chunk = blockIdx.x % 49;
    int row0  = b * Nn + chunk * 64;

    if (ITER == 0 && chunk == 0 && t < 32) {
        float a = 0.f;
        for (int j = 0; j < 98; j++) a += d_pspart[(b * 98 + j) * 32 + t];
        d_phisum[b * 32 + t] = a;
    }

    // stage full tile (phi: 512 f4, g: 1024 f4)
    {
        const float4* phg = (const float4*)(d_phi + row0 * 32);
        const float4* gg  = (const float4*)(g + row0 * 64);
        ((float4*)sph)[t]       = phg[t];
        ((float4*)sph)[t + 256] = phg[t + 256];
        ((float4*)sg)[t]        = gg[t];
        ((float4*)sg)[t + 256]  = gg[t + 256];
        ((float4*)sg)[t + 512]  = gg[t + 512];
        ((float4*)sg)[t + 768]  = gg[t + 768];
    }
    __syncthreads();

    int rg = t >> 7;              // row group 0..1 (32 rows each)
    int u  = t & 127;
    int d0 = (u >> 4) * 4;        // 0,4,...,28
    int c0 = (u & 15) * 4;        // 0,4,...,60

    float acc[4][4];
#pragma unroll
    for (int i = 0; i < 4; i++)
#pragma unroll
        for (int j = 0; j < 4; j++) acc[i][j] = 0.f;

    const float* P = sph + rg * 32 * 32;
    const float* G = sg + rg * 32 * 64;
#pragma unroll 8
    for (int j = 0; j < 32; j++) {
        float4 p  = *(const float4*)(P + j * 32 + d0);
        float4 gv = *(const float4*)(G + j * 64 + c0);
        acc[0][0] = fmaf(p.x, gv.x, acc[0][0]); acc[0][1] = fmaf(p.x, gv.y, acc[0][1]);
        acc[0][2] = fmaf(p.x, gv.z, acc[0][2]); acc[0][3] = fmaf(p.x, gv.w, acc[0][3]);
        acc[1][0] = fmaf(p.y, gv.x, acc[1][0]); acc[1][1] = fmaf(p.y, gv.y, acc[1][1]);
        acc[1][2] = fmaf(p.y, gv.z, acc[1][2]); acc[1][3] = fmaf(p.y, gv.w, acc[1][3]);
        acc[2][0] = fmaf(p.z, gv.x, acc[2][0]); acc[2][1] = fmaf(p.z, gv.y, acc[2][1]);
        acc[2][2] = fmaf(p.z, gv.z, acc[2][2]); acc[2][3] = fmaf(p.z, gv.w, acc[2][3]);
        acc[3][0] = fmaf(p.w, gv.x, acc[3][0]); acc[3][1] = fmaf(p.w, gv.y, acc[3][1]);
        acc[3][2] = fmaf(p.w, gv.z, acc[3][2]); acc[3][3] = fmaf(p.w, gv.w, acc[3][3]);
    }
    __syncthreads();   // staged tiles fully consumed; overlay partials

    // write partials: part[rg][d][c], row stride 68
    float* part = sm;
#pragma unroll
    for (int di = 0; di < 4; di++) {
        *(float4*)(part + rg * 2176 + (d0 + di) * 68 + c0) =
            make_float4(acc[di][0], acc[di][1], acc[di][2], acc[di][3]);
    }
    __syncthreads();

    // reduce 2 groups + emit (same layout/count as R8: 2x v4 per thread)
    int dd = t >> 3, cc = (t & 7) * 8;
    const float* p0 = part + dd * 68 + cc;
    float4 a0 = *(const float4*)(p0);
    float4 a1 = *(const float4*)(p0 + 4);
    float4 b0 = *(const float4*)(p0 + 2176);
    float4 b1 = *(const float4*)(p0 + 2176 + 4);
    float* Mb = d_M[ITER] + b * 2048 + dd * 64 + cc;
    redg_v4(Mb,     a0.x + b0.x, a0.y + b0.y, a0.z + b0.z, a0.w + b0.w);
    redg_v4(Mb + 4, a1.x + b1.x, a1.y + b1.y, a1.z + b1.z, a1.w + b1.w);
}

// ===========================================================================
// K3/K5: two-phase apply (R5-proven, unchanged).
//   phase1: raw = theta @ M (K=32); fg = (lam/N)*raw - (s/N)*g
//   phase2: o = fg @ W + bias; BN; ReLU; out = x + 0.05*o
template<int ITER>
__global__ void __launch_bounds__(256) k_apply(
        const float* __restrict__ x,
        const float* __restrict__ Wst, const float* __restrict__ bst,
        const float* __restrict__ gam, const float* __restrict__ bet,
        const float* __restrict__ mmean, const float* __restrict__ mvar,
        float* __restrict__ out_ext) {
    const float* gin = ITER ? d_g1 : x;
    float* out       = ITER ? out_ext : d_g1;

    __shared__ float sm[8800];
    float* sAt  = sm;          // theta^T [k=32][row 64] pad 68   (2176)
    float* sM   = sm + 2176;   // M [k=32][col 64] pad 68          (2176)
    float* sW   = sm + 4352;   // W [k=64][col 64] pad 68          (4352)
    float* sfgT = sm;          // fg^T [k=64][row 64] pad 68, overlays sAt+sM
    float* ss   = sm + 8704;   // 64
    float* sps  = sm + 8768;   // 32

    int t  = threadIdx.x;
    int r0 = blockIdx.x * 64;
    int b  = blockIdx.x / 49;

    // stage theta^T
#pragma unroll
    for (int j = 0; j < 2; j++) {
        int e = t + j * 256;
        int r = e >> 3, dd = (e & 7) * 4;
        float4 v = ((const float4*)(d_theta + r0 * 32))[e];
        sAt[(dd + 0) * 68 + r] = v.x;
        sAt[(dd + 1) * 68 + r] = v.y;
        sAt[(dd + 2) * 68 + r] = v.z;
        sAt[(dd + 3) * 68 + r] = v.w;
    }
    // stage M
    const float* Mi = d_M[ITER] + b * 2048;
#pragma unroll
    for (int j = 0; j < 2; j++) {
        int e = t + j * 256;
        int k = e >> 4, c4 = (e & 15) * 4;
        *(float4*)(sM + k * 68 + c4) = ((const float4*)Mi)[e];
    }
    // stage W
    const float* Wi = Wst + ITER * 4096;
#pragma unroll
    for (int j = 0; j < 4; j++) {
        int e = t + j * 256;
        int k = e >> 4, c4 = (e & 15) * 4;
        *(float4*)(sW + k * 68 + c4) = ((const float4*)Wi)[e];
    }
    if (t < 32) sps[t] = d_phisum[b * 32 + t];
    __syncthreads();

    if (t < 64) {   // -(s/N) per row, s = LAM * theta . phisum
        float a = 0.f;
#pragma unroll
        for (int k = 0; k < 32; k++) a = fmaf(sAt[k * 68 + t], sps[k], a);
        ss[t] = a * (-LAMF * INVN);
    }
    __syncthreads();

    int tx = t & 15, ty = t >> 4;
    int rr = ty * 4, cc = tx * 4;

    // ---- phase 1: raw = theta @ M (K=32) ----
    float fg[4][4];
#pragma unroll
    for (int i = 0; i < 4; i++)
#pragma unroll
        for (int j = 0; j < 4; j++) fg[i][j] = 0.f;

#pragma unroll 8
    for (int k = 0; k < 32; k++) {
        float4 a  = *(const float4*)(sAt + k * 68 + rr);
        float4 bv = *(const float4*)(sM + k * 68 + cc);
        fg[0][0] = fmaf(a.x, bv.x, fg[0][0]); fg[0][1] = fmaf(a.x, bv.y, fg[0][1]);
        fg[0][2] = fmaf(a.x, bv.z, fg[0][2]); fg[0][3] = fmaf(a.x, bv.w, fg[0][3]);
        fg[1][0] = fmaf(a.y, bv.x, fg[1][0]); fg[1][1] = fmaf(a.y, bv.y, fg[1][1]);
        fg[1][2] = fmaf(a.y, bv.z, fg[1][2]); fg[1][3] = fmaf(a.y, bv.w, fg[1][3]);
        fg[2][0] = fmaf(a.z, bv.x, fg[2][0]); fg[2][1] = fmaf(a.z, bv.y, fg[2][1]);
        fg[2][2] = fmaf(a.z, bv.z, fg[2][2]); fg[2][3] = fmaf(a.z, bv.w, fg[2][3]);
        fg[3][0] = fmaf(a.w, bv.x, fg[3][0]); fg[3][1] = fmaf(a.w, bv.y, fg[3][1]);
        fg[3][2] = fmaf(a.w, bv.z, fg[3][2]); fg[3][3] = fmaf(a.w, bv.w, fg[3][3]);
    }
    const float c1 = LAMF * INVN;
#pragma unroll
    for (int i = 0; i < 4; i++) {
        float sneg = ss[rr + i];
        float4 gv = *(const float4*)(gin + (r0 + rr + i) * 64 + cc);
        fg[i][0] = fmaf(sneg, gv.x, c1 * fg[i][0]);
        fg[i][1] = fmaf(sneg, gv.y, c1 * fg[i][1]);
        fg[i][2] = fmaf(sneg, gv.z, c1 * fg[i][2]);
        fg[i][3] = fmaf(sneg, gv.w, c1 * fg[i][3]);
    }
    __syncthreads();   // sAt/sM fully read; reuse as sfgT

    // store fg transposed: sfgT[k=col][row]
#pragma unroll
    for (int j = 0; j < 4; j++) {
        float4 v = make_float4(fg[0][j], fg[1][j], fg[2][j], fg[3][j]);
        *(float4*)(sfgT + (cc + j) * 68 + rr) = v;
    }
    __syncthreads();

    // ---- phase 2: o = fg @ W (K=64) ----
    float acc[4][4];
#pragma unroll
    for (int i = 0; i < 4; i++)
#pragma unroll
        for (int j = 0; j < 4; j++) acc[i][j] = 0.f;

#pragma unroll 8
    for (int k = 0; k < 64; k++) {
        float4 a  = *(const float4*)(sfgT + k * 68 + rr);
        float4 bv = *(const float4*)(sW + k * 68 + cc);
        acc[0][0] = fmaf(a.x, bv.x, acc[0][0]); acc[0][1] = fmaf(a.x, bv.y, acc[0][1]);
        acc[0][2] = fmaf(a.x, bv.z, acc[0][2]); acc[0][3] = fmaf(a.x, bv.w, acc[0][3]);
        acc[1][0] = fmaf(a.y, bv.x, acc[1][0]); acc[1][1] = fmaf(a.y, bv.y, acc[1][1]);
        acc[1][2] = fmaf(a.y, bv.z, acc[1][2]); acc[1][3] = fmaf(a.y, bv.w, acc[1][3]);
        acc[2][0] = fmaf(a.z, bv.x, acc[2][0]); acc[2][1] = fmaf(a.z, bv.y, acc[2][1]);
        acc[2][2] = fmaf(a.z, bv.z, acc[2][2]); acc[2][3] = fmaf(a.z, bv.w, acc[2][3]);
        acc[3][0] = fmaf(a.w, bv.x, acc[3][0]); acc[3][1] = fmaf(a.w, bv.y, acc[3][1]);
        acc[3][2] = fmaf(a.w, bv.z, acc[3][2]); acc[3][3] = fmaf(a.w, bv.w, acc[3][3]);
    }

    // epilogue: bias, BN, ReLU, residual (last == x always)
    float4 bias = *(const float4*)(bst + ITER * 64 + cc);
    float4 gm   = *(const float4*)(gam + ITER * 64 + cc);
    float4 bt4  = *(const float4*)(bet + ITER * 64 + cc);
    float4 mmv  = *(const float4*)(mmean + ITER * 64 + cc);
    float4 mv   = *(const float4*)(mvar + ITER * 64 + cc);
    float scl[4]  = { gm.x * rsqrtf(mv.x + BNEPS), gm.y * rsqrtf(mv.y + BNEPS),
                      gm.z * rsqrtf(mv.z + BNEPS), gm.w * rsqrtf(mv.w + BNEPS) };
    float bia[4]  = { bias.x, bias.y, bias.z, bias.w };
    float mean[4] = { mmv.x, mmv.y, mmv.z, mmv.w };
    float betc[4] = { bt4.x, bt4.y, bt4.z, bt4.w };

#pragma unroll
    for (int i = 0; i < 4; i++) {
        int r = r0 + rr + i;
        float4 xv = *(const float4*)(x + r * 64 + cc);
        float xa[4] = { xv.x, xv.y, xv.z, xv.w };
        float4 ov;
        float* op = (float*)&ov;
#pragma unroll
        for (int j = 0; j < 4; j++) {
            float o = acc[i][j] + bia[j];
            o = (o - mean[j]) * scl[j] + betc[j];
            o = fmaxf(o, 0.f);
            op[j] = xa[j] + HSTEP * o;
        }
        *(float4*)(out + r * 64 + cc) = ov;
    }
}

// ---------------------------------------------------------------------------
extern "C" void kernel_launch(void* const* d_in, const int* in_sizes, int n_in,
                              void* d_out, int out_size) {
    const float* x     = (const float*)d_in[0];
    const float* Wt    = (const float*)d_in[1];
    const float* bt    = (const float*)d_in[2];
    const float* Wp    = (const float*)d_in[3];
    const float* bp    = (const float*)d_in[4];
    const float* Wst   = (const float*)d_in[5];
    const float* bst   = (const float*)d_in[6];
    const float* gam   = (const float*)d_in[7];
    const float* bet   = (const float*)d_in[8];
    const float* mmean = (const float*)d_in[9];
    const float* mvar  = (const float*)d_in[10];
    float* out = (float*)d_out;

    k_theta_phi<<<BNROWS / 32, 256>>>(x, Wt, bt, Wp, bp);
    k_reduceM<0><<<Bb * 49, 256>>>(x);
    k_apply<0><<<BNROWS / 64, 256>>>(x, Wst, bst, gam, bet, mmean, mvar, out);
    k_reduceM<1><<<Bb * 49, 256>>>(x);
    k_apply<1><<<BNROWS / 64, 256>>>(x, Wst, bst, gam, bet, mmean, mvar, out);
}